// round 12
// baseline (speedup 1.0000x reference)
#include <cuda_runtime.h>
#include <cuda_bf16.h>
#include <math.h>

#define Bsz  2
#define Tlen 512
#define Cdim 1024
#define Hn   16
#define Dd   64
#define CSz  64
#define NCH  8
#define KCV  4

// ---------------- scratch (static device globals; no allocation) ----------------
__device__ float g_xq[Bsz*Tlen*Cdim];
__device__ float g_xk[Bsz*Tlen*Cdim];
__device__ float g_xv[Bsz*Tlen*Cdim];
__device__ float g_q [Bsz*Tlen*Cdim];
__device__ float g_k [Bsz*Tlen*Cdim];
__device__ float g_v [Bsz*Tlen*Cdim];
__device__ float g_alpha[Bsz*Tlen*Hn];
__device__ float g_eta  [Bsz*Tlen*Hn];
__device__ float g_theta[Bsz*Tlen*Hn];
__device__ float g_gamma[Bsz*Tlen*Hn];
__device__ float g_M[Bsz*Hn*Dd*Dd];
__device__ float g_S[Bsz*Hn*Dd*Dd];
__device__ float g_chunkS[(size_t)Bsz*CSz*Hn*Dd*Dd];   // 33.5 MB
__device__ float g_y [Bsz*Tlen*Cdim];
__device__ float g_yn[Bsz*Tlen*Cdim];

__constant__ float PEC[5][3] = {
    {8.28721201814563f, -23.595886519098837f, 17.300387312530933f},
    {4.107059111542203f, -2.9478499167379106f, 0.5448431082926601f},
    {3.9486908534822946f, -2.908902115962949f, 0.5518191394370137f},
    {3.3184196573706015f, -2.488488024314874f, 0.51004894012372f},
    {2.300652019954817f, -1.6689039845747493f, 0.4188073119525673f},
};

// ---------------- zero persistent state ----------------
__global__ void zero_state_kernel() {
    int i = blockIdx.x * blockDim.x + threadIdx.x;
    if (i < Bsz*Hn*Dd*Dd) { g_M[i] = 0.f; g_S[i] = 0.f; }
}

// ---------------- SGEMM NT: C[m,n] = sum_k A[m,k]*B[n,k] ----------------
__device__ __forceinline__ void sgemm_nt_body(
    const float* __restrict__ A, const float* __restrict__ B, float* __restrict__ C,
    int M, int N, int K, int bx, int by)
{
    __shared__ float As[64][17];
    __shared__ float Bs[64][17];
    int tx = threadIdx.x & 15, ty = threadIdx.x >> 4;
    int m0 = by * 64, n0 = bx * 64;
    float acc[4][4] = {};
    float cmp[4][4] = {};
    for (int k0 = 0; k0 < K; k0 += 16) {
        #pragma unroll
        for (int i = 0; i < 4; i++) {
            int e = threadIdx.x + 256*i;
            int r = e >> 4, kk = e & 15;
            As[r][kk] = A[(size_t)(m0+r)*K + k0 + kk];
            Bs[r][kk] = B[(size_t)(n0+r)*K + k0 + kk];
        }
        __syncthreads();
        float tacc[4][4] = {};
        #pragma unroll
        for (int kk = 0; kk < 16; kk++) {
            float ar[4], br[4];
            #pragma unroll
            for (int r = 0; r < 4; r++) ar[r] = As[ty*4+r][kk];
            #pragma unroll
            for (int c = 0; c < 4; c++) br[c] = Bs[tx*4+c][kk];
            #pragma unroll
            for (int r = 0; r < 4; r++)
                #pragma unroll
                for (int c = 0; c < 4; c++)
                    tacc[r][c] += ar[r]*br[c];
        }
        #pragma unroll
        for (int r = 0; r < 4; r++)
            #pragma unroll
            for (int c = 0; c < 4; c++) {
                float y = tacc[r][c] - cmp[r][c];
                float s = acc[r][c] + y;
                cmp[r][c] = (s - acc[r][c]) - y;
                acc[r][c] = s;
            }
        __syncthreads();
    }
    #pragma unroll
    for (int r = 0; r < 4; r++)
        #pragma unroll
        for (int c = 0; c < 4; c++)
            C[(size_t)(m0+ty*4+r)*N + n0 + tx*4 + c] = acc[r][c] - cmp[r][c];
}

__global__ __launch_bounds__(256) void sgemm_nt(
    const float* __restrict__ A, const float* __restrict__ B, float* __restrict__ C,
    int M, int N, int K)
{
    sgemm_nt_body(A, B, C, M, N, K, blockIdx.x, blockIdx.y);
}

__global__ __launch_bounds__(256) void sgemm_nt_qkv(
    const float* __restrict__ A,
    const float* __restrict__ Wq, const float* __restrict__ Wk, const float* __restrict__ Wv,
    float* __restrict__ Cq, float* __restrict__ Ck, float* __restrict__ Cv,
    int M, int N, int K)
{
    int z = blockIdx.z;
    const float* B = (z == 0) ? Wq : (z == 1) ? Wk : Wv;
    float*       C = (z == 0) ? Cq : (z == 1) ? Ck : Cv;
    sgemm_nt_body(A, B, C, M, N, K, blockIdx.x, blockIdx.y);
}

// ---------------- causal depthwise conv (+ optional rmsnorm+poly per head) ----------------
__global__ __launch_bounds__(256) void conv_feat_kernel(
    const float* __restrict__ xin, const float* __restrict__ w,
    const float* __restrict__ bias, float* __restrict__ outp, int do_norm)
{
    int bt = blockIdx.x;
    int b = bt / Tlen, t = bt % Tlen;
    int c0 = threadIdx.x * 4;
    float val[4];
    #pragma unroll
    for (int u = 0; u < 4; u++) {
        int c = c0 + u;
        float acc = bias[c];
        #pragma unroll
        for (int j = 0; j < KCV; j++) {
            int tt = t - (KCV-1) + j;
            if (tt >= 0) acc += w[c*KCV + j] * xin[(size_t)(b*Tlen + tt)*Cdim + c];
        }
        val[u] = acc;
    }
    if (do_norm) {
        float ss = val[0]*val[0] + val[1]*val[1] + val[2]*val[2] + val[3]*val[3];
        #pragma unroll
        for (int m = 1; m < 16; m <<= 1) ss += __shfl_xor_sync(0xffffffffu, ss, m);
        float r = rsqrtf(ss * (1.f/64.f) + 1e-6f);
        #pragma unroll
        for (int u = 0; u < 4; u++) {
            float xn = val[u] * r;
            val[u] = xn + 0.5f*xn*xn;
        }
    }
    float4* o4 = (float4*)(outp + (size_t)bt*Cdim + c0);
    *o4 = make_float4(val[0], val[1], val[2], val[3]);
}

// ---------------- final per-head rmsnorm of y ----------------
__global__ __launch_bounds__(256) void ynorm_kernel(
    const float* __restrict__ yin, float* __restrict__ outp)
{
    int bt = blockIdx.x;
    int c0 = threadIdx.x * 4;
    float val[4];
    #pragma unroll
    for (int u = 0; u < 4; u++) val[u] = yin[(size_t)bt*Cdim + c0 + u];
    float ss = val[0]*val[0] + val[1]*val[1] + val[2]*val[2] + val[3]*val[3];
    #pragma unroll
    for (int m = 1; m < 16; m <<= 1) ss += __shfl_xor_sync(0xffffffffu, ss, m);
    float r = rsqrtf(ss * (1.f/64.f) + 1e-6f);
    float4* o4 = (float4*)(outp + (size_t)bt*Cdim + c0);
    *o4 = make_float4(val[0]*r, val[1]*r, val[2]*r, val[3]*r);
}

// ---------------- gates: sigmoid(x @ W.T) for 4 weight matrices ----------------
__global__ __launch_bounds__(256) void gates_kernel(
    const float* __restrict__ x,
    const float* __restrict__ Wa, const float* __restrict__ We,
    const float* __restrict__ Wt, const float* __restrict__ Wg)
{
    __shared__ float xs[Cdim];
    int bt = blockIdx.x;
    int tid = threadIdx.x;
    #pragma unroll
    for (int i = 0; i < 4; i++) xs[tid + 256*i] = x[(size_t)bt*Cdim + tid + 256*i];
    __syncthreads();
    int oi = tid >> 2, part = tid & 3;
    int mat = oi >> 4, h = oi & 15;
    const float* W = (mat==0) ? Wa : (mat==1) ? We : (mat==2) ? Wt : Wg;
    W += h*Cdim + part*256;
    const float* xp = xs + part*256;
    float a0 = 0.f, a1 = 0.f, a2 = 0.f, a3 = 0.f;
    #pragma unroll 8
    for (int i = 0; i < 64; i++) {
        a0 += xp[i]      * W[i];
        a1 += xp[64+i]   * W[64+i];
        a2 += xp[128+i]  * W[128+i];
        a3 += xp[192+i]  * W[192+i];
    }
    float acc = (a0 + a1) + (a2 + a3);
    acc += __shfl_xor_sync(0xffffffffu, acc, 1);
    acc += __shfl_xor_sync(0xffffffffu, acc, 2);
    if (part == 0) {
        float s = 1.f/(1.f + expf(-acc));
        float* out = (mat==0) ? g_alpha : (mat==1) ? g_eta : (mat==2) ? g_theta : g_gamma;
        out[bt*Hn + h] = s;
    }
}

// ---------------- per-chunk: err, omega window, momentum scan -> g_chunkS ----------------
// v-partitioned: grid (Bsz*Hn, 4); each block owns 16 v-rows.  All global I/O float4.
__global__ __launch_bounds__(256) void chunk_err_kernel(
    const float* __restrict__ kbuf, const float* __restrict__ vbuf, int n)
{
    __shared__ float Ms[16*64];
    __shared__ float ks[64*64];
    __shared__ float e2[64*16];
    __shared__ float vs[64*16];
    __shared__ float gam[64], etas[64], thts[64];

    int bx = blockIdx.x;
    int b = bx >> 4, h = bx & 15;
    int v0 = blockIdx.y * 16;
    int tid = threadIdx.x;
    int v_loc = tid >> 4;      // 0..15
    int kq = tid & 15;         // k = kq*4 .. kq*4+3

    ((float4*)Ms)[tid] =
        ((const float4*)(g_M + (size_t)(b*Hn + h)*4096 + v0*64))[tid];
    for (int i = tid; i < 1024; i += 256) {
        int t = i >> 4, c4 = (i & 15)*4;
        *(float4*)(ks + t*64 + c4) =
            *(const float4*)(kbuf + (size_t)(b*Tlen + n*CSz + t)*Cdim + h*Dd + c4);
    }
    {
        int t = tid >> 2, c4 = (tid & 3)*4;
        *(float4*)(vs + t*16 + c4) =
            *(const float4*)(vbuf + (size_t)(b*Tlen + n*CSz + t)*Cdim + h*Dd + v0 + c4);
    }
    if (tid < 64) {
        int tg = (b*Tlen + n*CSz + tid)*Hn + h;
        gam[tid]  = g_gamma[tg];
        etas[tid] = g_eta[tg];
        thts[tid] = g_theta[tg];
    }
    float4 sreg = *(const float4*)(g_S + (size_t)(b*Hn + h)*4096 + (v0+v_loc)*64 + kq*4);
    __syncthreads();

    // e2[t][v] = 2*(dot(M[v,:], k_t) - v_t[v]);  16 lanes per v
    {
        float4 m4 = *(const float4*)(Ms + v_loc*64 + kq*4);
        for (int t = 0; t < 64; t++) {
            float4 k4 = *(const float4*)(ks + t*64 + kq*4);
            float p = m4.x*k4.x + m4.y*k4.y + m4.z*k4.z + m4.w*k4.w;
            p += __shfl_xor_sync(0xffffffffu, p, 1);
            p += __shfl_xor_sync(0xffffffffu, p, 2);
            p += __shfl_xor_sync(0xffffffffu, p, 4);
            p += __shfl_xor_sync(0xffffffffu, p, 8);
            if (kq == 0) e2[t*16 + v_loc] = 2.f*(p - vs[t*16 + v_loc]);
        }
    }
    __syncthreads();

    // omega window + momentum scan; store chunk_S (float4)
    for (int t = 0; t < 64; t++) {
        float ax = 0.f, ay = 0.f, az = 0.f, aw = 0.f;
        #pragma unroll
        for (int w = 0; w < 8; w++) {
            int iw = t - 7 + w;
            if (iw >= 0) {
                float ge = gam[iw] * e2[iw*16 + v_loc];
                float4 k4 = *(const float4*)(ks + iw*64 + kq*4);
                ax += ge*k4.x; ay += ge*k4.y; az += ge*k4.z; aw += ge*k4.w;
            }
        }
        float neta = -etas[t], th = thts[t];
        sreg.x = th*sreg.x + neta*ax;
        sreg.y = th*sreg.y + neta*ay;
        sreg.z = th*sreg.z + neta*az;
        sreg.w = th*sreg.w + neta*aw;
        *(float4*)(g_chunkS + ((((size_t)b*CSz + t)*Hn + h)*Dd + (v0+v_loc))*Dd + kq*4) = sreg;
    }
    *(float4*)(g_S + (size_t)(b*Hn + h)*4096 + (v0+v_loc)*64 + kq*4) = sreg;
}

// ---------------- Polar Express (in-place on g_chunkS), one 64x64 matrix per block ----------------
// Packed f32x2 rewrite: all matmuls in NT form (rows . rows) so k-pairs are
// memory-adjacent and FFMA2 (fma.rn.f32x2, 2 fp32 ops/issue) halves the fp
// floor.  NT legality: mm1 = NT(X,X); mm2 uses S1 exactly symmetric (threads
// (i,j)/(j,i) run bitwise-identical chains) = NT(S1,S1); mm3 = NT(S2,XT).
// Layout: pitch-64 + XOR swizzle (k4 ^ (row>>2))&15 -> all LDS/STS conflict-free.
// Precision: packed Kahan iters 0-1 (sub via exact fma(x,-1,y)); iters 2-4 plain
// (the two f32x2 lanes ARE the 2-way split accumulator).
typedef unsigned long long u64;

__device__ __forceinline__ u64 f2pack(float lo, float hi) {
    u64 r; asm("mov.b64 %0, {%1,%2};" : "=l"(r) : "f"(lo), "f"(hi)); return r;
}
__device__ __forceinline__ void f2unpack(u64 v, float& lo, float& hi) {
    asm("mov.b64 {%0,%1}, %2;" : "=f"(lo), "=f"(hi) : "l"(v));
}
__device__ __forceinline__ u64 f2fma(u64 a, u64 b, u64 c) {
    u64 d; asm("fma.rn.f32x2 %0, %1, %2, %3;" : "=l"(d) : "l"(a), "l"(b), "l"(c)); return d;
}
__device__ __forceinline__ u64 f2add(u64 a, u64 b) {
    u64 d; asm("add.rn.f32x2 %0, %1, %2;" : "=l"(d) : "l"(a), "l"(b)); return d;
}
__device__ __forceinline__ u64 f2mul(u64 a, u64 b) {
    u64 d; asm("mul.rn.f32x2 %0, %1, %2;" : "=l"(d) : "l"(a), "l"(b)); return d;
}

#define SWOFF(row, k4) (((row) << 6) + (((((k4) ^ ((row) >> 2))) & 15) << 2))
#define PE_SMEM (4*64*64*4)   // 65,536 B -> 2 blocks/SM (reg-capped anyway)

template<bool KAHAN>
__device__ __forceinline__ void mmNT2(
    const float* __restrict__ A, const float* __restrict__ Bt,
    float o[4][4], int i0, int j0)
{
    const u64 NEG1 = f2pack(-1.f, -1.f);
    u64 acc[4][4] = {};
    u64 aux[4][4] = {};
    #pragma unroll 4
    for (int kb = 0; kb < 16; kb++) {
        u64 ap[4][2], bp[4][2];
        #pragma unroll
        for (int r = 0; r < 4; r++) {
            float4 f = *(const float4*)(A + SWOFF(i0+r, kb));
            ap[r][0] = f2pack(f.x, f.y); ap[r][1] = f2pack(f.z, f.w);
        }
        #pragma unroll
        for (int c = 0; c < 4; c++) {
            float4 f = *(const float4*)(Bt + SWOFF(j0+c, kb));
            bp[c][0] = f2pack(f.x, f.y); bp[c][1] = f2pack(f.z, f.w);
        }
        #pragma unroll
        for (int kp = 0; kp < 2; kp++)
            #pragma unroll
            for (int r = 0; r < 4; r++)
                #pragma unroll
                for (int c = 0; c < 4; c++) {
                    if (KAHAN) {
                        u64 p = f2mul(ap[r][kp], bp[c][kp]);
                        u64 y = f2fma(aux[r][c], NEG1, p);     // p - aux
                        u64 s = f2add(acc[r][c], y);
                        u64 d = f2fma(acc[r][c], NEG1, s);     // s - acc
                        aux[r][c] = f2fma(y, NEG1, d);         // d - y
                        acc[r][c] = s;
                    } else {
                        acc[r][c] = f2fma(ap[r][kp], bp[c][kp], acc[r][c]);
                    }
                }
    }
    #pragma unroll
    for (int r = 0; r < 4; r++)
        #pragma unroll
        for (int c = 0; c < 4; c++) {
            u64 t = KAHAN ? f2fma(aux[r][c], NEG1, acc[r][c]) : acc[r][c];
            float lo, hi; f2unpack(t, lo, hi);
            o[r][c] = lo + hi;
        }
}

template<bool KAHAN>
__device__ __forceinline__ void pe_iterNT(
    float* X, float* XT, float* S1, float* S2,
    int i0, int j0, int tx, int ty, float ca, float cb, float cc, bool needT)
{
    float o[4][4];
    // S1 = X @ X^T   (NT: rows of X . rows of X; result exactly symmetric)
    mmNT2<KAHAN>(X, X, o, i0, j0);
    #pragma unroll
    for (int r = 0; r < 4; r++)
        *(float4*)(S1 + SWOFF(i0+r, tx)) = make_float4(o[r][0], o[r][1], o[r][2], o[r][3]);
    __syncthreads();
    // S2 = cb*S1 + cc*(S1 @ S1)   (S1 symmetric -> NT(S1,S1); S2 symmetric)
    mmNT2<KAHAN>(S1, S1, o, i0, j0);
    #pragma unroll
    for (int r = 0; r < 4; r++) {
        float4 t = *(const float4*)(S1 + SWOFF(i0+r, tx));
        *(float4*)(S2 + SWOFF(i0+r, tx)) =
            make_float4(cb*t.x + cc*o[r][0], cb*t.y + cc*o[r][1],
                        cb*t.z + cc*o[r][2], cb*t.w + cc*o[r][3]);
    }
    __syncthreads();
    // Y = ca*X + S2 @ X   (NT(S2, XT)) -> S1;  Y^T -> XT (after all XT reads done)
    mmNT2<KAHAN>(S2, XT, o, i0, j0);
    #pragma unroll
    for (int r = 0; r < 4; r++) {
        float4 x = *(const float4*)(X + SWOFF(i0+r, tx));
        o[r][0] += ca*x.x; o[r][1] += ca*x.y; o[r][2] += ca*x.z; o[r][3] += ca*x.w;
        *(float4*)(S1 + SWOFF(i0+r, tx)) = make_float4(o[r][0], o[r][1], o[r][2], o[r][3]);
    }
    __syncthreads();   // everyone finished reading XT (and S1 stores visible)
    if (needT) {
        #pragma unroll
        for (int c = 0; c < 4; c++)
            *(float4*)(XT + SWOFF(j0+c, ty)) = make_float4(o[0][c], o[1][c], o[2][c], o[3][c]);
        __syncthreads();
    }
}

__global__ __launch_bounds__(256, 2) void pe_kernel()
{
    extern __shared__ float sm[];
    float* X  = sm;
    float* XT = sm +   64*64;
    float* S1 = sm + 2*64*64;
    float* S2 = sm + 3*64*64;
    __shared__ float red[8];
    __shared__ float snorm;

    int tid = threadIdx.x;
    int tx = tid & 15, ty = tid >> 4;
    int i0 = ty*4, j0 = tx*4;
    float* gp = g_chunkS + (size_t)blockIdx.x * 4096;

    // load (vectorized, swizzled) + Frobenius norm
    float lsum = 0.f;
    for (int i = tid; i < 1024; i += 256) {
        float4 f = ((const float4*)gp)[i];
        int row = i >> 4, k4 = i & 15;
        *(float4*)(X + SWOFF(row, k4)) = f;
        lsum += f.x*f.x + f.y*f.y + f.z*f.z + f.w*f.w;
    }
    #pragma unroll
    for (int m = 16; m >= 1; m >>= 1) lsum += __shfl_xor_sync(0xffffffffu, lsum, m);
    if ((tid & 31) == 0) red[tid >> 5] = lsum;
    __syncthreads();
    if (tid < 8) {
        float r2 = red[tid];
        r2 += __shfl_xor_sync(0xffu, r2, 4);
        r2 += __shfl_xor_sync(0xffu, r2, 2);
        r2 += __shfl_xor_sync(0xffu, r2, 1);
        if (tid == 0) snorm = 1.f/((sqrtf(r2) + 1e-7f)*1.01f);
    }
    __syncthreads();
    // scale in place + build X^T
    {
        float sc = snorm;
        float t[4][4];
        #pragma unroll
        for (int r = 0; r < 4; r++) {
            float4 f = *(const float4*)(X + SWOFF(i0+r, tx));
            t[r][0] = f.x*sc; t[r][1] = f.y*sc; t[r][2] = f.z*sc; t[r][3] = f.w*sc;
            *(float4*)(X + SWOFF(i0+r, tx)) = make_float4(t[r][0], t[r][1], t[r][2], t[r][3]);
        }
        #pragma unroll
        for (int c = 0; c < 4; c++)
            *(float4*)(XT + SWOFF(j0+c, ty)) = make_float4(t[0][c], t[1][c], t[2][c], t[3][c]);
    }
    __syncthreads();

    // iters 0-1: packed Kahan (amplified ~124x / ~30x downstream)
    pe_iterNT<true>(X, XT, S1, S2, i0, j0, tx, ty, PEC[0][0], PEC[0][1], PEC[0][2], true);
    { float* tmp = X; X = S1; S1 = tmp; }
    pe_iterNT<true>(X, XT, S1, S2, i0, j0, tx, ty, PEC[1][0], PEC[1][1], PEC[1][2], true);
    { float* tmp = X; X = S1; S1 = tmp; }
    // iters 2-4: plain packed FMA (lanes = 2-way split accumulators)
    #pragma unroll 1
    for (int it = 2; it < 5; it++) {
        pe_iterNT<false>(X, XT, S1, S2, i0, j0, tx, ty,
                         PEC[it][0], PEC[it][1], PEC[it][2], it < 4);
        float* tmp = X; X = S1; S1 = tmp;
    }

    // store result (unswizzle)
    for (int i = tid; i < 1024; i += 256) {
        int row = i >> 4, k4 = i & 15;
        float4 f = *(const float4*)(X + SWOFF(row, k4));
        ((float4*)gp)[i] = f;
    }
}

// ---------------- per-chunk: memory scan M_t = a_t M_{t-1} + orth_t ; y_t = M_t q_t ----------------
// v-partitioned: grid (Bsz*Hn, 4); all global I/O float4.
__global__ __launch_bounds__(256) void memscan_kernel(const float* __restrict__ qbuf, int n)
{
    __shared__ float qs[64*64];
    __shared__ float al[64];
    int bx = blockIdx.x;
    int b = bx >> 4, h = bx & 15;
    int v0 = blockIdx.y * 16;
    int tid = threadIdx.x;
    int v_loc = tid >> 4, kq = tid & 15;

    for (int i = tid; i < 1024; i += 256) {
        int t = i >> 4, c4 = (i & 15)*4;
        *(float4*)(qs + t*64 + c4) =
            *(const float4*)(qbuf + (size_t)(b*Tlen + n*CSz + t)*Cdim + h*Dd + c4);
    }
    if (tid < 64) al[tid] = g_alpha[(b*Tlen + n*CSz + tid)*Hn + h];
    float4 mreg = *(const float4*)(g_M + (size_t)(b*Hn + h)*4096 + (v0+v_loc)*64 + kq*4);
    __syncthreads();

    for (int t = 0; t < 64; t++) {
        float a = al[t];
        float4 cs = *(const float4*)(g_chunkS + ((((size_t)b*CSz + t)*Hn + h)*Dd + (v0+v_loc))*Dd + kq*4);
        mreg.x = a*mreg.x + cs.x;
        mreg.y = a*mreg.y + cs.y;
        mreg.z = a*mreg.z + cs.z;
        mreg.w = a*mreg.w + cs.w;
        float4 q4 = *(const float4*)(qs + t*64 + kq*4);
        float p = mreg.x*q4.x + mreg.y*q4.y + mreg.z*q4.z + mreg.w*q4.w;
        p += __shfl_xor_sync(0xffffffffu, p, 1);
        p += __shfl_xor_sync(0xffffffffu, p, 2);
        p += __shfl_xor_sync(0xffffffffu, p, 4);
        p += __shfl_xor_sync(0xffffffffu, p, 8);
        if (kq == 0)
            g_y[(size_t)(b*Tlen + n*CSz + t)*Cdim + h*Dd + v0 + v_loc] = p;
    }
    *(float4*)(g_M + (size_t)(b*Hn + h)*4096 + (v0+v_loc)*64 + kq*4) = mreg;
}

// ---------------- launch ----------------
extern "C" void kernel_launch(void* const* d_in, const int* in_sizes, int n_in,
                              void* d_out, int out_size)
{
    const float* x   = (const float*)d_in[0];
    const float* Wq  = (const float*)d_in[1];
    const float* Wk  = (const float*)d_in[2];
    const float* Wv  = (const float*)d_in[3];
    const float* Wo  = (const float*)d_in[4];
    const float* cqw = (const float*)d_in[5];
    const float* cqb = (const float*)d_in[6];
    const float* ckw = (const float*)d_in[7];
    const float* ckb = (const float*)d_in[8];
    const float* cvw = (const float*)d_in[9];
    const float* cvb = (const float*)d_in[10];
    const float* Wa  = (const float*)d_in[11];
    const float* We  = (const float*)d_in[12];
    const float* Wt  = (const float*)d_in[13];
    const float* Wg  = (const float*)d_in[14];
    float* out = (float*)d_out;

    cudaFuncSetAttribute(pe_kernel, cudaFuncAttributeMaxDynamicSharedMemorySize, PE_SMEM);

    float *pxq, *pxk, *pxv, *pq, *pk, *pv, *py, *pyn;
    cudaGetSymbolAddress((void**)&pxq, g_xq);
    cudaGetSymbolAddress((void**)&pxk, g_xk);
    cudaGetSymbolAddress((void**)&pxv, g_xv);
    cudaGetSymbolAddress((void**)&pq,  g_q);
    cudaGetSymbolAddress((void**)&pk,  g_k);
    cudaGetSymbolAddress((void**)&pv,  g_v);
    cudaGetSymbolAddress((void**)&py,  g_y);
    cudaGetSymbolAddress((void**)&pyn, g_yn);

    zero_state_kernel<<<(Bsz*Hn*Dd*Dd + 255)/256, 256>>>();

    dim3 gq(Cdim/64, (Bsz*Tlen)/64, 3);
    sgemm_nt_qkv<<<gq, 256>>>(x, Wq, Wk, Wv, pxq, pxk, pxv, Bsz*Tlen, Cdim, Cdim);
    gates_kernel<<<Bsz*Tlen, 256>>>(x, Wa, We, Wt, Wg);
    conv_feat_kernel<<<Bsz*Tlen, 256>>>(pxq, cqw, cqb, pq, 1);
    conv_feat_kernel<<<Bsz*Tlen, 256>>>(pxk, ckw, ckb, pk, 1);
    conv_feat_kernel<<<Bsz*Tlen, 256>>>(pxv, cvw, cvb, pv, 0);

    dim3 gscan(Bsz*Hn, 4);
    for (int n = 0; n < NCH; n++) {
        chunk_err_kernel<<<gscan, 256>>>(pk, pv, n);
        pe_kernel<<<Bsz*CSz*Hn, 256, PE_SMEM>>>();
        memscan_kernel<<<gscan, 256>>>(pq, n);
    }

    ynorm_kernel<<<Bsz*Tlen, 256>>>(py, pyn);
    dim3 gg(Cdim/64, (Bsz*Tlen)/64);
    sgemm_nt<<<gg, 256>>>(pyn, Wo, out, Bsz*Tlen, Cdim, Cdim);
}

// round 13
// speedup vs baseline: 1.2684x; 1.2684x over previous
#include <cuda_runtime.h>
#include <cuda_bf16.h>
#include <math.h>

#define Bsz  2
#define Tlen 512
#define Cdim 1024
#define Hn   16
#define Dd   64
#define CSz  64
#define NCH  8
#define KCV  4

// ---------------- scratch (static device globals; no allocation) ----------------
__device__ float g_xq[Bsz*Tlen*Cdim];
__device__ float g_xk[Bsz*Tlen*Cdim];
__device__ float g_xv[Bsz*Tlen*Cdim];
__device__ float g_q [Bsz*Tlen*Cdim];
__device__ float g_k [Bsz*Tlen*Cdim];
__device__ float g_v [Bsz*Tlen*Cdim];
__device__ float g_alpha[Bsz*Tlen*Hn];
__device__ float g_eta  [Bsz*Tlen*Hn];
__device__ float g_theta[Bsz*Tlen*Hn];
__device__ float g_gamma[Bsz*Tlen*Hn];
__device__ float g_M[Bsz*Hn*Dd*Dd];
__device__ float g_S[Bsz*Hn*Dd*Dd];
__device__ float g_chunkS[(size_t)Bsz*CSz*Hn*Dd*Dd];   // 33.5 MB
__device__ float g_y [Bsz*Tlen*Cdim];
__device__ float g_yn[Bsz*Tlen*Cdim];

__constant__ float PEC[5][3] = {
    {8.28721201814563f, -23.595886519098837f, 17.300387312530933f},
    {4.107059111542203f, -2.9478499167379106f, 0.5448431082926601f},
    {3.9486908534822946f, -2.908902115962949f, 0.5518191394370137f},
    {3.3184196573706015f, -2.488488024314874f, 0.51004894012372f},
    {2.300652019954817f, -1.6689039845747493f, 0.4188073119525673f},
};

// ---------------- zero persistent state ----------------
__global__ void zero_state_kernel() {
    int i = blockIdx.x * blockDim.x + threadIdx.x;
    if (i < Bsz*Hn*Dd*Dd) { g_M[i] = 0.f; g_S[i] = 0.f; }
}

// ---------------- SGEMM NT: C[m,n] = sum_k A[m,k]*B[n,k] ----------------
// Vectorized global loads (LDG.128); scalar smem stores keep the conflict-free
// pitch-17 compute layout.  Arithmetic order identical to the proven version.
__device__ __forceinline__ void sgemm_nt_body(
    const float* __restrict__ A, const float* __restrict__ B, float* __restrict__ C,
    int M, int N, int K, int bx, int by)
{
    __shared__ float As[64][17];
    __shared__ float Bs[64][17];
    int tx = threadIdx.x & 15, ty = threadIdx.x >> 4;
    int m0 = by * 64, n0 = bx * 64;
    int lr = threadIdx.x >> 2;          // 0..63
    int lk = (threadIdx.x & 3) * 4;     // 0,4,8,12
    float acc[4][4] = {};
    float cmp[4][4] = {};
    for (int k0 = 0; k0 < K; k0 += 16) {
        float4 av = *(const float4*)(A + (size_t)(m0+lr)*K + k0 + lk);
        float4 bv = *(const float4*)(B + (size_t)(n0+lr)*K + k0 + lk);
        As[lr][lk+0] = av.x; As[lr][lk+1] = av.y; As[lr][lk+2] = av.z; As[lr][lk+3] = av.w;
        Bs[lr][lk+0] = bv.x; Bs[lr][lk+1] = bv.y; Bs[lr][lk+2] = bv.z; Bs[lr][lk+3] = bv.w;
        __syncthreads();
        float tacc[4][4] = {};
        #pragma unroll
        for (int kk = 0; kk < 16; kk++) {
            float ar[4], br[4];
            #pragma unroll
            for (int r = 0; r < 4; r++) ar[r] = As[ty*4+r][kk];
            #pragma unroll
            for (int c = 0; c < 4; c++) br[c] = Bs[tx*4+c][kk];
            #pragma unroll
            for (int r = 0; r < 4; r++)
                #pragma unroll
                for (int c = 0; c < 4; c++)
                    tacc[r][c] += ar[r]*br[c];
        }
        #pragma unroll
        for (int r = 0; r < 4; r++)
            #pragma unroll
            for (int c = 0; c < 4; c++) {
                float y = tacc[r][c] - cmp[r][c];
                float s = acc[r][c] + y;
                cmp[r][c] = (s - acc[r][c]) - y;
                acc[r][c] = s;
            }
        __syncthreads();
    }
    #pragma unroll
    for (int r = 0; r < 4; r++)
        #pragma unroll
        for (int c = 0; c < 4; c++)
            C[(size_t)(m0+ty*4+r)*N + n0 + tx*4 + c] = acc[r][c] - cmp[r][c];
}

__global__ __launch_bounds__(256) void sgemm_nt(
    const float* __restrict__ A, const float* __restrict__ B, float* __restrict__ C,
    int M, int N, int K)
{
    sgemm_nt_body(A, B, C, M, N, K, blockIdx.x, blockIdx.y);
}

__global__ __launch_bounds__(256) void sgemm_nt_qkv(
    const float* __restrict__ A,
    const float* __restrict__ Wq, const float* __restrict__ Wk, const float* __restrict__ Wv,
    float* __restrict__ Cq, float* __restrict__ Ck, float* __restrict__ Cv,
    int M, int N, int K)
{
    int z = blockIdx.z;
    const float* B = (z == 0) ? Wq : (z == 1) ? Wk : Wv;
    float*       C = (z == 0) ? Cq : (z == 1) ? Ck : Cv;
    sgemm_nt_body(A, B, C, M, N, K, blockIdx.x, blockIdx.y);
}

// ---------------- causal depthwise conv (+ optional rmsnorm+poly per head) ----------------
__global__ __launch_bounds__(256) void conv_feat_kernel(
    const float* __restrict__ xin, const float* __restrict__ w,
    const float* __restrict__ bias, float* __restrict__ outp, int do_norm)
{
    int bt = blockIdx.x;
    int b = bt / Tlen, t = bt % Tlen;
    int c0 = threadIdx.x * 4;
    float val[4];
    #pragma unroll
    for (int u = 0; u < 4; u++) {
        int c = c0 + u;
        float acc = bias[c];
        #pragma unroll
        for (int j = 0; j < KCV; j++) {
            int tt = t - (KCV-1) + j;
            if (tt >= 0) acc += w[c*KCV + j] * xin[(size_t)(b*Tlen + tt)*Cdim + c];
        }
        val[u] = acc;
    }
    if (do_norm) {
        float ss = val[0]*val[0] + val[1]*val[1] + val[2]*val[2] + val[3]*val[3];
        #pragma unroll
        for (int m = 1; m < 16; m <<= 1) ss += __shfl_xor_sync(0xffffffffu, ss, m);
        float r = rsqrtf(ss * (1.f/64.f) + 1e-6f);
        #pragma unroll
        for (int u = 0; u < 4; u++) {
            float xn = val[u] * r;
            val[u] = xn + 0.5f*xn*xn;
        }
    }
    float4* o4 = (float4*)(outp + (size_t)bt*Cdim + c0);
    *o4 = make_float4(val[0], val[1], val[2], val[3]);
}

// ---------------- final per-head rmsnorm of y ----------------
__global__ __launch_bounds__(256) void ynorm_kernel(
    const float* __restrict__ yin, float* __restrict__ outp)
{
    int bt = blockIdx.x;
    int c0 = threadIdx.x * 4;
    float val[4];
    #pragma unroll
    for (int u = 0; u < 4; u++) val[u] = yin[(size_t)bt*Cdim + c0 + u];
    float ss = val[0]*val[0] + val[1]*val[1] + val[2]*val[2] + val[3]*val[3];
    #pragma unroll
    for (int m = 1; m < 16; m <<= 1) ss += __shfl_xor_sync(0xffffffffu, ss, m);
    float r = rsqrtf(ss * (1.f/64.f) + 1e-6f);
    float4* o4 = (float4*)(outp + (size_t)bt*Cdim + c0);
    *o4 = make_float4(val[0]*r, val[1]*r, val[2]*r, val[3]*r);
}

// ---------------- gates: sigmoid(x @ W.T) for 4 weight matrices ----------------
__global__ __launch_bounds__(256) void gates_kernel(
    const float* __restrict__ x,
    const float* __restrict__ Wa, const float* __restrict__ We,
    const float* __restrict__ Wt, const float* __restrict__ Wg)
{
    __shared__ float xs[Cdim];
    int bt = blockIdx.x;
    int tid = threadIdx.x;
    #pragma unroll
    for (int i = 0; i < 4; i++) xs[tid + 256*i] = x[(size_t)bt*Cdim + tid + 256*i];
    __syncthreads();
    int oi = tid >> 2, part = tid & 3;
    int mat = oi >> 4, h = oi & 15;
    const float* W = (mat==0) ? Wa : (mat==1) ? We : (mat==2) ? Wt : Wg;
    W += h*Cdim + part*256;
    const float* xp = xs + part*256;
    float a0 = 0.f, a1 = 0.f, a2 = 0.f, a3 = 0.f;
    #pragma unroll 8
    for (int i = 0; i < 64; i++) {
        a0 += xp[i]      * W[i];
        a1 += xp[64+i]   * W[64+i];
        a2 += xp[128+i]  * W[128+i];
        a3 += xp[192+i]  * W[192+i];
    }
    float acc = (a0 + a1) + (a2 + a3);
    acc += __shfl_xor_sync(0xffffffffu, acc, 1);
    acc += __shfl_xor_sync(0xffffffffu, acc, 2);
    if (part == 0) {
        float s = 1.f/(1.f + expf(-acc));
        float* out = (mat==0) ? g_alpha : (mat==1) ? g_eta : (mat==2) ? g_theta : g_gamma;
        out[bt*Hn + h] = s;
    }
}

// ---------------- per-chunk: err, omega window, momentum scan -> g_chunkS ----------------
// v-partitioned: grid (Bsz*Hn, 4); each block owns 16 v-rows.  All global I/O float4.
__global__ __launch_bounds__(256) void chunk_err_kernel(
    const float* __restrict__ kbuf, const float* __restrict__ vbuf, int n)
{
    __shared__ float Ms[16*64];
    __shared__ float ks[64*64];
    __shared__ float e2[64*16];
    __shared__ float vs[64*16];
    __shared__ float gam[64], etas[64], thts[64];

    int bx = blockIdx.x;
    int b = bx >> 4, h = bx & 15;
    int v0 = blockIdx.y * 16;
    int tid = threadIdx.x;
    int v_loc = tid >> 4;      // 0..15
    int kq = tid & 15;         // k = kq*4 .. kq*4+3

    ((float4*)Ms)[tid] =
        ((const float4*)(g_M + (size_t)(b*Hn + h)*4096 + v0*64))[tid];
    for (int i = tid; i < 1024; i += 256) {
        int t = i >> 4, c4 = (i & 15)*4;
        *(float4*)(ks + t*64 + c4) =
            *(const float4*)(kbuf + (size_t)(b*Tlen + n*CSz + t)*Cdim + h*Dd + c4);
    }
    {
        int t = tid >> 2, c4 = (tid & 3)*4;
        *(float4*)(vs + t*16 + c4) =
            *(const float4*)(vbuf + (size_t)(b*Tlen + n*CSz + t)*Cdim + h*Dd + v0 + c4);
    }
    if (tid < 64) {
        int tg = (b*Tlen + n*CSz + tid)*Hn + h;
        gam[tid]  = g_gamma[tg];
        etas[tid] = g_eta[tg];
        thts[tid] = g_theta[tg];
    }
    float4 sreg = *(const float4*)(g_S + (size_t)(b*Hn + h)*4096 + (v0+v_loc)*64 + kq*4);
    __syncthreads();

    // e2[t][v] = 2*(dot(M[v,:], k_t) - v_t[v]);  16 lanes per v
    {
        float4 m4 = *(const float4*)(Ms + v_loc*64 + kq*4);
        for (int t = 0; t < 64; t++) {
            float4 k4 = *(const float4*)(ks + t*64 + kq*4);
            float p = m4.x*k4.x + m4.y*k4.y + m4.z*k4.z + m4.w*k4.w;
            p += __shfl_xor_sync(0xffffffffu, p, 1);
            p += __shfl_xor_sync(0xffffffffu, p, 2);
            p += __shfl_xor_sync(0xffffffffu, p, 4);
            p += __shfl_xor_sync(0xffffffffu, p, 8);
            if (kq == 0) e2[t*16 + v_loc] = 2.f*(p - vs[t*16 + v_loc]);
        }
    }
    __syncthreads();

    // omega window + momentum scan; store chunk_S (float4)
    for (int t = 0; t < 64; t++) {
        float ax = 0.f, ay = 0.f, az = 0.f, aw = 0.f;
        #pragma unroll
        for (int w = 0; w < 8; w++) {
            int iw = t - 7 + w;
            if (iw >= 0) {
                float ge = gam[iw] * e2[iw*16 + v_loc];
                float4 k4 = *(const float4*)(ks + iw*64 + kq*4);
                ax += ge*k4.x; ay += ge*k4.y; az += ge*k4.z; aw += ge*k4.w;
            }
        }
        float neta = -etas[t], th = thts[t];
        sreg.x = th*sreg.x + neta*ax;
        sreg.y = th*sreg.y + neta*ay;
        sreg.z = th*sreg.z + neta*az;
        sreg.w = th*sreg.w + neta*aw;
        *(float4*)(g_chunkS + ((((size_t)b*CSz + t)*Hn + h)*Dd + (v0+v_loc))*Dd + kq*4) = sreg;
    }
    *(float4*)(g_S + (size_t)(b*Hn + h)*4096 + (v0+v_loc)*64 + kq*4) = sreg;
}

// ---------------- Polar Express (in-place on g_chunkS), one 64x64 matrix per block ----------------
// Round-11 proven arithmetic (pitch-68, float4 smem, explicit X^T; Kahan iters
// 0-1, plain split iters 2-4) + SYMMETRY HALVING: S1 = X@X^T and
// S2 = cb*S1 + cc*S1^2 are symmetric, so only the 136 upper-triangle 4x4 tiles
// (threads 0..135 = warps 0..4) are computed; each tile is mirrored bitwise to
// its transpose slot.  Warps 5-7 idle through mm1+mm2 -> SM-level issue for
// those phases drops to 5/8.  Tile values are byte-identical to round 11.
#define PPITCH 68
#define PE_SMEM (4*64*PPITCH*4)   // 69,632 B -> 3 blocks/SM

template<bool KAHAN>
__device__ __forceinline__ void mmP(
    const float* __restrict__ A, const float* __restrict__ B,
    float o[4][4], int i0, int j0)
{
    float acc[4][4] = {};
    float aux[4][4] = {};   // Kahan compensation OR second split accumulator
    #pragma unroll 4
    for (int kb = 0; kb < 16; kb++) {
        const int k0 = kb*4;
        float4 a4[4], b4[4];
        #pragma unroll
        for (int r = 0; r < 4; r++)
            a4[r] = *(const float4*)(A + (i0+r)*PPITCH + k0);
        #pragma unroll
        for (int kk = 0; kk < 4; kk++)
            b4[kk] = *(const float4*)(B + (k0+kk)*PPITCH + j0);
        #pragma unroll
        for (int kk = 0; kk < 4; kk++) {
            float ar[4], br[4];
            br[0] = b4[kk].x; br[1] = b4[kk].y; br[2] = b4[kk].z; br[3] = b4[kk].w;
            #pragma unroll
            for (int r = 0; r < 4; r++) ar[r] = ((const float*)&a4[r])[kk];
            if (KAHAN) {
                #pragma unroll
                for (int r = 0; r < 4; r++)
                    #pragma unroll
                    for (int c = 0; c < 4; c++) {
                        float p = ar[r]*br[c];
                        float y = p - aux[r][c];
                        float s = acc[r][c] + y;
                        aux[r][c] = (s - acc[r][c]) - y;
                        acc[r][c] = s;
                    }
            } else {
                if (kk & 1) {
                    #pragma unroll
                    for (int r = 0; r < 4; r++)
                        #pragma unroll
                        for (int c = 0; c < 4; c++) aux[r][c] += ar[r]*br[c];
                } else {
                    #pragma unroll
                    for (int r = 0; r < 4; r++)
                        #pragma unroll
                        for (int c = 0; c < 4; c++) acc[r][c] += ar[r]*br[c];
                }
            }
        }
    }
    #pragma unroll
    for (int r = 0; r < 4; r++)
        #pragma unroll
        for (int c = 0; c < 4; c++)
            o[r][c] = KAHAN ? (acc[r][c] - aux[r][c]) : (acc[r][c] + aux[r][c]);
}

// Note: mm1's B operand is XT, accessed as B[k*PPITCH + j0] = XT[k][j] = X[j][k],
// so mmP(X, XT) computes X@X^T exactly as round 11 did.
template<bool KAHAN>
__device__ __forceinline__ void pe_iterT(
    float* X, float* XT, float* S1, float* S2,
    int i0, int j0,                 // full-grid tile (mm3)
    int ti0, int tj0, bool act,     // triangle tile (mm1, mm2); act = tid < 136
    float ca, float cb, float cc, bool needT)
{
    float o[4][4];
    // mm1: S1 = X @ X^T  (triangle threads only; mirror to transpose slot)
    if (act) {
        mmP<KAHAN>(X, XT, o, ti0, tj0);
        #pragma unroll
        for (int r = 0; r < 4; r++)
            *(float4*)(S1 + (ti0+r)*PPITCH + tj0) = make_float4(o[r][0], o[r][1], o[r][2], o[r][3]);
        if (ti0 != tj0) {
            #pragma unroll
            for (int c = 0; c < 4; c++)
                *(float4*)(S1 + (tj0+c)*PPITCH + ti0) = make_float4(o[0][c], o[1][c], o[2][c], o[3][c]);
        }
    }
    __syncthreads();
    // mm2: S2 = cb*S1 + cc*(S1@S1)  (triangle; S1 symmetric so transpose slot
    // uses the same S1 tile values — bitwise symmetric result)
    if (act) {
        mmP<KAHAN>(S1, S1, o, ti0, tj0);
        float4 t4[4];
        #pragma unroll
        for (int r = 0; r < 4; r++) {
            t4[r] = *(const float4*)(S1 + (ti0+r)*PPITCH + tj0);
            *(float4*)(S2 + (ti0+r)*PPITCH + tj0) =
                make_float4(cb*t4[r].x + cc*o[r][0], cb*t4[r].y + cc*o[r][1],
                            cb*t4[r].z + cc*o[r][2], cb*t4[r].w + cc*o[r][3]);
        }
        if (ti0 != tj0) {
            #pragma unroll
            for (int c = 0; c < 4; c++) {
                // S2[tj0+c][ti0+r] = cb*S1[tj0+c][ti0+r] + cc*(S1@S1)[tj0+c][ti0+r]
                //                  = cb*S1[ti0+r][tj0+c] + cc*o[r][c]   (symmetry)
                float4 v;
                v.x = cb*((const float*)&t4[0])[c] + cc*o[0][c];
                v.y = cb*((const float*)&t4[1])[c] + cc*o[1][c];
                v.z = cb*((const float*)&t4[2])[c] + cc*o[2][c];
                v.w = cb*((const float*)&t4[3])[c] + cc*o[3][c];
                *(float4*)(S2 + (tj0+c)*PPITCH + ti0) = v;
            }
        }
    }
    __syncthreads();
    // mm3: Y = ca*X + S2 @ X  -> S1 (full grid);  Y^T -> XT
    mmP<KAHAN>(S2, X, o, i0, j0);
    #pragma unroll
    for (int r = 0; r < 4; r++) {
        float4 x = *(const float4*)(X + (i0+r)*PPITCH + j0);
        o[r][0] += ca*x.x; o[r][1] += ca*x.y; o[r][2] += ca*x.z; o[r][3] += ca*x.w;
        *(float4*)(S1 + (i0+r)*PPITCH + j0) = make_float4(o[r][0], o[r][1], o[r][2], o[r][3]);
    }
    if (needT) {
        #pragma unroll
        for (int c = 0; c < 4; c++)
            *(float4*)(XT + (j0+c)*PPITCH + i0) = make_float4(o[0][c], o[1][c], o[2][c], o[3][c]);
    }
    __syncthreads();
}

__global__ __launch_bounds__(256) void pe_kernel()
{
    extern __shared__ float sm[];
    float* X  = sm;
    float* XT = sm +   64*PPITCH;
    float* S1 = sm + 2*64*PPITCH;
    float* S2 = sm + 3*64*PPITCH;
    __shared__ float red[8];
    __shared__ float snorm;

    int tid = threadIdx.x;
    int tx = tid & 15, ty = tid >> 4;
    int i0 = ty*4, j0 = tx*4;
    float* gp = g_chunkS + (size_t)blockIdx.x * 4096;

    // triangle tile assignment: threads 0..135 -> (ta,tb), 0 <= ta <= tb <= 15
    bool act = (tid < 136);
    int ta = 0, tb = 0;
    if (act) {
        int rem = tid;
        while (rem >= 16 - ta) { rem -= 16 - ta; ta++; }
        tb = ta + rem;
    }
    int ti0 = ta*4, tj0 = tb*4;

    // load (vectorized) + Frobenius norm
    float lsum = 0.f;
    for (int i = tid; i < 1024; i += 256) {
        float4 f = ((const float4*)gp)[i];
        int row = i >> 4, c4 = (i & 15) * 4;
        *(float4*)(X + row*PPITCH + c4) = f;
        lsum += f.x*f.x + f.y*f.y + f.z*f.z + f.w*f.w;
    }
    #pragma unroll
    for (int m = 16; m >= 1; m >>= 1) lsum += __shfl_xor_sync(0xffffffffu, lsum, m);
    if ((tid & 31) == 0) red[tid >> 5] = lsum;
    __syncthreads();
    if (tid < 8) {
        float r2 = red[tid];
        r2 += __shfl_xor_sync(0xffu, r2, 4);
        r2 += __shfl_xor_sync(0xffu, r2, 2);
        r2 += __shfl_xor_sync(0xffu, r2, 1);
        if (tid == 0) snorm = 1.f/((sqrtf(r2) + 1e-7f)*1.01f);
    }
    __syncthreads();
    // scale in place + build X^T
    {
        float sc = snorm;
        float t[4][4];
        #pragma unroll
        for (int r = 0; r < 4; r++) {
            float4 f = *(const float4*)(X + (i0+r)*PPITCH + j0);
            t[r][0] = f.x*sc; t[r][1] = f.y*sc; t[r][2] = f.z*sc; t[r][3] = f.w*sc;
            *(float4*)(X + (i0+r)*PPITCH + j0) = make_float4(t[r][0], t[r][1], t[r][2], t[r][3]);
        }
        #pragma unroll
        for (int c = 0; c < 4; c++)
            *(float4*)(XT + (j0+c)*PPITCH + i0) = make_float4(t[0][c], t[1][c], t[2][c], t[3][c]);
    }
    __syncthreads();

    // iters 0-1: Kahan (amplified ~124x / ~30x downstream)
    pe_iterT<true>(X, XT, S1, S2, i0, j0, ti0, tj0, act, PEC[0][0], PEC[0][1], PEC[0][2], true);
    { float* tmp = X; X = S1; S1 = tmp; }
    pe_iterT<true>(X, XT, S1, S2, i0, j0, ti0, tj0, act, PEC[1][0], PEC[1][1], PEC[1][2], true);
    { float* tmp = X; X = S1; S1 = tmp; }
    // iters 2-4: plain split accumulators
    #pragma unroll 1
    for (int it = 2; it < 5; it++) {
        pe_iterT<false>(X, XT, S1, S2, i0, j0, ti0, tj0, act,
                        PEC[it][0], PEC[it][1], PEC[it][2], it < 4);
        float* tmp = X; X = S1; S1 = tmp;
    }

    #pragma unroll
    for (int r = 0; r < 4; r++) {
        float4 f = *(const float4*)(X + (i0+r)*PPITCH + j0);
        *(float4*)(gp + (i0+r)*64 + j0) = f;
    }
}

// ---------------- per-chunk: memory scan M_t = a_t M_{t-1} + orth_t ; y_t = M_t q_t ----------------
// v-partitioned: grid (Bsz*Hn, 4); all global I/O float4.
__global__ __launch_bounds__(256) void memscan_kernel(const float* __restrict__ qbuf, int n)
{
    __shared__ float qs[64*64];
    __shared__ float al[64];
    int bx = blockIdx.x;
    int b = bx >> 4, h = bx & 15;
    int v0 = blockIdx.y * 16;
    int tid = threadIdx.x;
    int v_loc = tid >> 4, kq = tid & 15;

    for (int i = tid; i < 1024; i += 256) {
        int t = i >> 4, c4 = (i & 15)*4;
        *(float4*)(qs + t*64 + c4) =
            *(const float4*)(qbuf + (size_t)(b*Tlen + n*CSz + t)*Cdim + h*Dd + c4);
    }
    if (tid < 64) al[tid] = g_alpha[(b*Tlen + n*CSz + tid)*Hn + h];
    float4 mreg = *(const float4*)(g_M + (size_t)(b*Hn + h)*4096 + (v0+v_loc)*64 + kq*4);
    __syncthreads();

    for (int t = 0; t < 64; t++) {
        float a = al[t];
        float4 cs = *(const float4*)(g_chunkS + ((((size_t)b*CSz + t)*Hn + h)*Dd + (v0+v_loc))*Dd + kq*4);
        mreg.x = a*mreg.x + cs.x;
        mreg.y = a*mreg.y + cs.y;
        mreg.z = a*mreg.z + cs.z;
        mreg.w = a*mreg.w + cs.w;
        float4 q4 = *(const float4*)(qs + t*64 + kq*4);
        float p = mreg.x*q4.x + mreg.y*q4.y + mreg.z*q4.z + mreg.w*q4.w;
        p += __shfl_xor_sync(0xffffffffu, p, 1);
        p += __shfl_xor_sync(0xffffffffu, p, 2);
        p += __shfl_xor_sync(0xffffffffu, p, 4);
        p += __shfl_xor_sync(0xffffffffu, p, 8);
        if (kq == 0)
            g_y[(size_t)(b*Tlen + n*CSz + t)*Cdim + h*Dd + v0 + v_loc] = p;
    }
    *(float4*)(g_M + (size_t)(b*Hn + h)*4096 + (v0+v_loc)*64 + kq*4) = mreg;
}

// ---------------- launch ----------------
extern "C" void kernel_launch(void* const* d_in, const int* in_sizes, int n_in,
                              void* d_out, int out_size)
{
    const float* x   = (const float*)d_in[0];
    const float* Wq  = (const float*)d_in[1];
    const float* Wk  = (const float*)d_in[2];
    const float* Wv  = (const float*)d_in[3];
    const float* Wo  = (const float*)d_in[4];
    const float* cqw = (const float*)d_in[5];
    const float* cqb = (const float*)d_in[6];
    const float* ckw = (const float*)d_in[7];
    const float* ckb = (const float*)d_in[8];
    const float* cvw = (const float*)d_in[9];
    const float* cvb = (const float*)d_in[10];
    const float* Wa  = (const float*)d_in[11];
    const float* We  = (const float*)d_in[12];
    const float* Wt  = (const float*)d_in[13];
    const float* Wg  = (const float*)d_in[14];
    float* out = (float*)d_out;

    cudaFuncSetAttribute(pe_kernel, cudaFuncAttributeMaxDynamicSharedMemorySize, PE_SMEM);

    float *pxq, *pxk, *pxv, *pq, *pk, *pv, *py, *pyn;
    cudaGetSymbolAddress((void**)&pxq, g_xq);
    cudaGetSymbolAddress((void**)&pxk, g_xk);
    cudaGetSymbolAddress((void**)&pxv, g_xv);
    cudaGetSymbolAddress((void**)&pq,  g_q);
    cudaGetSymbolAddress((void**)&pk,  g_k);
    cudaGetSymbolAddress((void**)&pv,  g_v);
    cudaGetSymbolAddress((void**)&py,  g_y);
    cudaGetSymbolAddress((void**)&pyn, g_yn);

    zero_state_kernel<<<(Bsz*Hn*Dd*Dd + 255)/256, 256>>>();

    dim3 gq(Cdim/64, (Bsz*Tlen)/64, 3);
    sgemm_nt_qkv<<<gq, 256>>>(x, Wq, Wk, Wv, pxq, pxk, pxv, Bsz*Tlen, Cdim, Cdim);
    gates_kernel<<<Bsz*Tlen, 256>>>(x, Wa, We, Wt, Wg);
    conv_feat_kernel<<<Bsz*Tlen, 256>>>(pxq, cqw, cqb, pq, 1);
    conv_feat_kernel<<<Bsz*Tlen, 256>>>(pxk, ckw, ckb, pk, 1);
    conv_feat_kernel<<<Bsz*Tlen, 256>>>(pxv, cvw, cvb, pv, 0);

    dim3 gscan(Bsz*Hn, 4);
    for (int n = 0; n < NCH; n++) {
        chunk_err_kernel<<<gscan, 256>>>(pk, pv, n);
        pe_kernel<<<Bsz*CSz*Hn, 256, PE_SMEM>>>();
        memscan_kernel<<<gscan, 256>>>(pq, n);
    }

    ynorm_kernel<<<Bsz*Tlen, 256>>>(py, pyn);
    dim3 gg(Cdim/64, (Bsz*Tlen)/64);
    sgemm_nt<<<gg, 256>>>(pyn, Wo, out, Bsz*Tlen, Cdim, Cdim);
}

// round 14
// speedup vs baseline: 1.5774x; 1.2436x over previous
#include <cuda_runtime.h>
#include <cuda_bf16.h>
#include <math.h>

#define Bsz  2
#define Tlen 512
#define Cdim 1024
#define Hn   16
#define Dd   64
#define CSz  64
#define NCH  8
#define KCV  4

// ---------------- scratch (static device globals; no allocation) ----------------
__device__ float g_xq[Bsz*Tlen*Cdim];
__device__ float g_xk[Bsz*Tlen*Cdim];
__device__ float g_xv[Bsz*Tlen*Cdim];
__device__ float g_q [Bsz*Tlen*Cdim];
__device__ float g_k [Bsz*Tlen*Cdim];
__device__ float g_v [Bsz*Tlen*Cdim];
__device__ float g_alpha[Bsz*Tlen*Hn];
__device__ float g_eta  [Bsz*Tlen*Hn];
__device__ float g_theta[Bsz*Tlen*Hn];
__device__ float g_gamma[Bsz*Tlen*Hn];
__device__ float g_M[Bsz*Hn*Dd*Dd];
__device__ float g_S[Bsz*Hn*Dd*Dd];
__device__ float g_chunkS[(size_t)Bsz*CSz*Hn*Dd*Dd];   // 33.5 MB
__device__ float g_y [Bsz*Tlen*Cdim];
__device__ float g_yn[Bsz*Tlen*Cdim];

__constant__ float PEC[5][3] = {
    {8.28721201814563f, -23.595886519098837f, 17.300387312530933f},
    {4.107059111542203f, -2.9478499167379106f, 0.5448431082926601f},
    {3.9486908534822946f, -2.908902115962949f, 0.5518191394370137f},
    {3.3184196573706015f, -2.488488024314874f, 0.51004894012372f},
    {2.300652019954817f, -1.6689039845747493f, 0.4188073119525673f},
};

// ---------------- zero persistent state ----------------
__global__ void zero_state_kernel() {
    int i = blockIdx.x * blockDim.x + threadIdx.x;
    if (i < Bsz*Hn*Dd*Dd) { g_M[i] = 0.f; g_S[i] = 0.f; }
}

// ---------------- SGEMM NT: C[m,n] = sum_k A[m,k]*B[n,k] ----------------
__device__ __forceinline__ void sgemm_nt_body(
    const float* __restrict__ A, const float* __restrict__ B, float* __restrict__ C,
    int M, int N, int K, int bx, int by)
{
    __shared__ float As[64][17];
    __shared__ float Bs[64][17];
    int tx = threadIdx.x & 15, ty = threadIdx.x >> 4;
    int m0 = by * 64, n0 = bx * 64;
    int lr = threadIdx.x >> 2;          // 0..63
    int lk = (threadIdx.x & 3) * 4;     // 0,4,8,12
    float acc[4][4] = {};
    float cmp[4][4] = {};
    for (int k0 = 0; k0 < K; k0 += 16) {
        float4 av = *(const float4*)(A + (size_t)(m0+lr)*K + k0 + lk);
        float4 bv = *(const float4*)(B + (size_t)(n0+lr)*K + k0 + lk);
        As[lr][lk+0] = av.x; As[lr][lk+1] = av.y; As[lr][lk+2] = av.z; As[lr][lk+3] = av.w;
        Bs[lr][lk+0] = bv.x; Bs[lr][lk+1] = bv.y; Bs[lr][lk+2] = bv.z; Bs[lr][lk+3] = bv.w;
        __syncthreads();
        float tacc[4][4] = {};
        #pragma unroll
        for (int kk = 0; kk < 16; kk++) {
            float ar[4], br[4];
            #pragma unroll
            for (int r = 0; r < 4; r++) ar[r] = As[ty*4+r][kk];
            #pragma unroll
            for (int c = 0; c < 4; c++) br[c] = Bs[tx*4+c][kk];
            #pragma unroll
            for (int r = 0; r < 4; r++)
                #pragma unroll
                for (int c = 0; c < 4; c++)
                    tacc[r][c] += ar[r]*br[c];
        }
        #pragma unroll
        for (int r = 0; r < 4; r++)
            #pragma unroll
            for (int c = 0; c < 4; c++) {
                float y = tacc[r][c] - cmp[r][c];
                float s = acc[r][c] + y;
                cmp[r][c] = (s - acc[r][c]) - y;
                acc[r][c] = s;
            }
        __syncthreads();
    }
    #pragma unroll
    for (int r = 0; r < 4; r++)
        #pragma unroll
        for (int c = 0; c < 4; c++)
            C[(size_t)(m0+ty*4+r)*N + n0 + tx*4 + c] = acc[r][c] - cmp[r][c];
}

__global__ __launch_bounds__(256) void sgemm_nt(
    const float* __restrict__ A, const float* __restrict__ B, float* __restrict__ C,
    int M, int N, int K)
{
    sgemm_nt_body(A, B, C, M, N, K, blockIdx.x, blockIdx.y);
}

__global__ __launch_bounds__(256) void sgemm_nt_qkv(
    const float* __restrict__ A,
    const float* __restrict__ Wq, const float* __restrict__ Wk, const float* __restrict__ Wv,
    float* __restrict__ Cq, float* __restrict__ Ck, float* __restrict__ Cv,
    int M, int N, int K)
{
    int z = blockIdx.z;
    const float* B = (z == 0) ? Wq : (z == 1) ? Wk : Wv;
    float*       C = (z == 0) ? Cq : (z == 1) ? Ck : Cv;
    sgemm_nt_body(A, B, C, M, N, K, blockIdx.x, blockIdx.y);
}

// ---------------- causal depthwise conv (+ optional rmsnorm+poly per head) ----------------
__global__ __launch_bounds__(256) void conv_feat_kernel(
    const float* __restrict__ xin, const float* __restrict__ w,
    const float* __restrict__ bias, float* __restrict__ outp, int do_norm)
{
    int bt = blockIdx.x;
    int b = bt / Tlen, t = bt % Tlen;
    int c0 = threadIdx.x * 4;
    float val[4];
    #pragma unroll
    for (int u = 0; u < 4; u++) {
        int c = c0 + u;
        float acc = bias[c];
        #pragma unroll
        for (int j = 0; j < KCV; j++) {
            int tt = t - (KCV-1) + j;
            if (tt >= 0) acc += w[c*KCV + j] * xin[(size_t)(b*Tlen + tt)*Cdim + c];
        }
        val[u] = acc;
    }
    if (do_norm) {
        float ss = val[0]*val[0] + val[1]*val[1] + val[2]*val[2] + val[3]*val[3];
        #pragma unroll
        for (int m = 1; m < 16; m <<= 1) ss += __shfl_xor_sync(0xffffffffu, ss, m);
        float r = rsqrtf(ss * (1.f/64.f) + 1e-6f);
        #pragma unroll
        for (int u = 0; u < 4; u++) {
            float xn = val[u] * r;
            val[u] = xn + 0.5f*xn*xn;
        }
    }
    float4* o4 = (float4*)(outp + (size_t)bt*Cdim + c0);
    *o4 = make_float4(val[0], val[1], val[2], val[3]);
}

// ---------------- final per-head rmsnorm of y ----------------
__global__ __launch_bounds__(256) void ynorm_kernel(
    const float* __restrict__ yin, float* __restrict__ outp)
{
    int bt = blockIdx.x;
    int c0 = threadIdx.x * 4;
    float val[4];
    #pragma unroll
    for (int u = 0; u < 4; u++) val[u] = yin[(size_t)bt*Cdim + c0 + u];
    float ss = val[0]*val[0] + val[1]*val[1] + val[2]*val[2] + val[3]*val[3];
    #pragma unroll
    for (int m = 1; m < 16; m <<= 1) ss += __shfl_xor_sync(0xffffffffu, ss, m);
    float r = rsqrtf(ss * (1.f/64.f) + 1e-6f);
    float4* o4 = (float4*)(outp + (size_t)bt*Cdim + c0);
    *o4 = make_float4(val[0]*r, val[1]*r, val[2]*r, val[3]*r);
}

// ---------------- gates: sigmoid(x @ W.T) for 4 weight matrices ----------------
__global__ __launch_bounds__(256) void gates_kernel(
    const float* __restrict__ x,
    const float* __restrict__ Wa, const float* __restrict__ We,
    const float* __restrict__ Wt, const float* __restrict__ Wg)
{
    __shared__ float xs[Cdim];
    int bt = blockIdx.x;
    int tid = threadIdx.x;
    #pragma unroll
    for (int i = 0; i < 4; i++) xs[tid + 256*i] = x[(size_t)bt*Cdim + tid + 256*i];
    __syncthreads();
    int oi = tid >> 2, part = tid & 3;
    int mat = oi >> 4, h = oi & 15;
    const float* W = (mat==0) ? Wa : (mat==1) ? We : (mat==2) ? Wt : Wg;
    W += h*Cdim + part*256;
    const float* xp = xs + part*256;
    float a0 = 0.f, a1 = 0.f, a2 = 0.f, a3 = 0.f;
    #pragma unroll 8
    for (int i = 0; i < 64; i++) {
        a0 += xp[i]      * W[i];
        a1 += xp[64+i]   * W[64+i];
        a2 += xp[128+i]  * W[128+i];
        a3 += xp[192+i]  * W[192+i];
    }
    float acc = (a0 + a1) + (a2 + a3);
    acc += __shfl_xor_sync(0xffffffffu, acc, 1);
    acc += __shfl_xor_sync(0xffffffffu, acc, 2);
    if (part == 0) {
        float s = 1.f/(1.f + expf(-acc));
        float* out = (mat==0) ? g_alpha : (mat==1) ? g_eta : (mat==2) ? g_theta : g_gamma;
        out[bt*Hn + h] = s;
    }
}

// ---------------- per-chunk: err, omega window, momentum scan -> g_chunkS ----------------
// v-partitioned: grid (Bsz*Hn, 4); each block owns 16 v-rows.  All global I/O float4.
__global__ __launch_bounds__(256) void chunk_err_kernel(
    const float* __restrict__ kbuf, const float* __restrict__ vbuf, int n)
{
    __shared__ float Ms[16*64];
    __shared__ float ks[64*64];
    __shared__ float e2[64*16];
    __shared__ float vs[64*16];
    __shared__ float gam[64], etas[64], thts[64];

    int bx = blockIdx.x;
    int b = bx >> 4, h = bx & 15;
    int v0 = blockIdx.y * 16;
    int tid = threadIdx.x;
    int v_loc = tid >> 4;      // 0..15
    int kq = tid & 15;         // k = kq*4 .. kq*4+3

    ((float4*)Ms)[tid] =
        ((const float4*)(g_M + (size_t)(b*Hn + h)*4096 + v0*64))[tid];
    for (int i = tid; i < 1024; i += 256) {
        int t = i >> 4, c4 = (i & 15)*4;
        *(float4*)(ks + t*64 + c4) =
            *(const float4*)(kbuf + (size_t)(b*Tlen + n*CSz + t)*Cdim + h*Dd + c4);
    }
    {
        int t = tid >> 2, c4 = (tid & 3)*4;
        *(float4*)(vs + t*16 + c4) =
            *(const float4*)(vbuf + (size_t)(b*Tlen + n*CSz + t)*Cdim + h*Dd + v0 + c4);
    }
    if (tid < 64) {
        int tg = (b*Tlen + n*CSz + tid)*Hn + h;
        gam[tid]  = g_gamma[tg];
        etas[tid] = g_eta[tg];
        thts[tid] = g_theta[tg];
    }
    float4 sreg = *(const float4*)(g_S + (size_t)(b*Hn + h)*4096 + (v0+v_loc)*64 + kq*4);
    __syncthreads();

    // e2[t][v] = 2*(dot(M[v,:], k_t) - v_t[v]);  16 lanes per v
    {
        float4 m4 = *(const float4*)(Ms + v_loc*64 + kq*4);
        for (int t = 0; t < 64; t++) {
            float4 k4 = *(const float4*)(ks + t*64 + kq*4);
            float p = m4.x*k4.x + m4.y*k4.y + m4.z*k4.z + m4.w*k4.w;
            p += __shfl_xor_sync(0xffffffffu, p, 1);
            p += __shfl_xor_sync(0xffffffffu, p, 2);
            p += __shfl_xor_sync(0xffffffffu, p, 4);
            p += __shfl_xor_sync(0xffffffffu, p, 8);
            if (kq == 0) e2[t*16 + v_loc] = 2.f*(p - vs[t*16 + v_loc]);
        }
    }
    __syncthreads();

    // omega window + momentum scan; store chunk_S (float4)
    for (int t = 0; t < 64; t++) {
        float ax = 0.f, ay = 0.f, az = 0.f, aw = 0.f;
        #pragma unroll
        for (int w = 0; w < 8; w++) {
            int iw = t - 7 + w;
            if (iw >= 0) {
                float ge = gam[iw] * e2[iw*16 + v_loc];
                float4 k4 = *(const float4*)(ks + iw*64 + kq*4);
                ax += ge*k4.x; ay += ge*k4.y; az += ge*k4.z; aw += ge*k4.w;
            }
        }
        float neta = -etas[t], th = thts[t];
        sreg.x = th*sreg.x + neta*ax;
        sreg.y = th*sreg.y + neta*ay;
        sreg.z = th*sreg.z + neta*az;
        sreg.w = th*sreg.w + neta*aw;
        *(float4*)(g_chunkS + ((((size_t)b*CSz + t)*Hn + h)*Dd + (v0+v_loc))*Dd + kq*4) = sreg;
    }
    *(float4*)(g_S + (size_t)(b*Hn + h)*4096 + (v0+v_loc)*64 + kq*4) = sreg;
}

// ---------------- Polar Express (in-place on g_chunkS), one 64x64 matrix per block ----------------
// Round-13 structure (pitch-68, float4 smem, explicit X^T, symmetry halving of
// mm1/mm2) + PAIRED-PRODUCT KAHAN: adjacent k-products fused via
// p = fma(a1,b1, a0*b0) before each Kahan fold -> 3 ops/product instead of 5,
// with NO extra register arrays (the round-10 group-fold trap).  Intra-pair sum
// is plain (<=1 ulp of the pair); the running sum stays compensated at the fp32
// floor, so iter-0's ~124x amplification sees the same noise as full Kahan.
#define PPITCH 68
#define PE_SMEM (4*64*PPITCH*4)   // 69,632 B -> 3 blocks/SM

template<bool KAHAN>
__device__ __forceinline__ void mmP(
    const float* __restrict__ A, const float* __restrict__ B,
    float o[4][4], int i0, int j0)
{
    float acc[4][4] = {};
    float aux[4][4] = {};   // Kahan compensation OR second split accumulator
    #pragma unroll 4
    for (int kb = 0; kb < 16; kb++) {
        const int k0 = kb*4;
        float4 a4[4], b4[4];
        #pragma unroll
        for (int r = 0; r < 4; r++)
            a4[r] = *(const float4*)(A + (i0+r)*PPITCH + k0);
        #pragma unroll
        for (int kk = 0; kk < 4; kk++)
            b4[kk] = *(const float4*)(B + (k0+kk)*PPITCH + j0);
        if (KAHAN) {
            // paired-product Kahan: one fold per 2 products
            #pragma unroll
            for (int kp = 0; kp < 2; kp++) {
                const int kk0 = 2*kp, kk1 = 2*kp + 1;
                float ar0[4], ar1[4], br0[4], br1[4];
                #pragma unroll
                for (int r = 0; r < 4; r++) {
                    ar0[r] = ((const float*)&a4[r])[kk0];
                    ar1[r] = ((const float*)&a4[r])[kk1];
                }
                #pragma unroll
                for (int c = 0; c < 4; c++) {
                    br0[c] = ((const float*)&b4[kk0])[c];
                    br1[c] = ((const float*)&b4[kk1])[c];
                }
                #pragma unroll
                for (int r = 0; r < 4; r++)
                    #pragma unroll
                    for (int c = 0; c < 4; c++) {
                        float p = fmaf(ar1[r], br1[c], ar0[r]*br0[c]);
                        float y = p - aux[r][c];
                        float s = acc[r][c] + y;
                        aux[r][c] = (s - acc[r][c]) - y;
                        acc[r][c] = s;
                    }
            }
        } else {
            #pragma unroll
            for (int kk = 0; kk < 4; kk++) {
                float ar[4], br[4];
                br[0] = b4[kk].x; br[1] = b4[kk].y; br[2] = b4[kk].z; br[3] = b4[kk].w;
                #pragma unroll
                for (int r = 0; r < 4; r++) ar[r] = ((const float*)&a4[r])[kk];
                if (kk & 1) {
                    #pragma unroll
                    for (int r = 0; r < 4; r++)
                        #pragma unroll
                        for (int c = 0; c < 4; c++) aux[r][c] += ar[r]*br[c];
                } else {
                    #pragma unroll
                    for (int r = 0; r < 4; r++)
                        #pragma unroll
                        for (int c = 0; c < 4; c++) acc[r][c] += ar[r]*br[c];
                }
            }
        }
    }
    #pragma unroll
    for (int r = 0; r < 4; r++)
        #pragma unroll
        for (int c = 0; c < 4; c++)
            o[r][c] = KAHAN ? (acc[r][c] - aux[r][c]) : (acc[r][c] + aux[r][c]);
}

// Note: mm1's B operand is XT, accessed as B[k*PPITCH + j0] = XT[k][j] = X[j][k],
// so mmP(X, XT) computes X@X^T.
template<bool KAHAN>
__device__ __forceinline__ void pe_iterT(
    float* X, float* XT, float* S1, float* S2,
    int i0, int j0,                 // full-grid tile (mm3)
    int ti0, int tj0, bool act,     // triangle tile (mm1, mm2); act = tid < 136
    float ca, float cb, float cc, bool needT)
{
    float o[4][4];
    // mm1: S1 = X @ X^T  (triangle threads only; mirror to transpose slot)
    if (act) {
        mmP<KAHAN>(X, XT, o, ti0, tj0);
        #pragma unroll
        for (int r = 0; r < 4; r++)
            *(float4*)(S1 + (ti0+r)*PPITCH + tj0) = make_float4(o[r][0], o[r][1], o[r][2], o[r][3]);
        if (ti0 != tj0) {
            #pragma unroll
            for (int c = 0; c < 4; c++)
                *(float4*)(S1 + (tj0+c)*PPITCH + ti0) = make_float4(o[0][c], o[1][c], o[2][c], o[3][c]);
        }
    }
    __syncthreads();
    // mm2: S2 = cb*S1 + cc*(S1@S1)  (triangle; symmetric result mirrored)
    if (act) {
        mmP<KAHAN>(S1, S1, o, ti0, tj0);
        float4 t4[4];
        #pragma unroll
        for (int r = 0; r < 4; r++) {
            t4[r] = *(const float4*)(S1 + (ti0+r)*PPITCH + tj0);
            *(float4*)(S2 + (ti0+r)*PPITCH + tj0) =
                make_float4(cb*t4[r].x + cc*o[r][0], cb*t4[r].y + cc*o[r][1],
                            cb*t4[r].z + cc*o[r][2], cb*t4[r].w + cc*o[r][3]);
        }
        if (ti0 != tj0) {
            #pragma unroll
            for (int c = 0; c < 4; c++) {
                float4 v;
                v.x = cb*((const float*)&t4[0])[c] + cc*o[0][c];
                v.y = cb*((const float*)&t4[1])[c] + cc*o[1][c];
                v.z = cb*((const float*)&t4[2])[c] + cc*o[2][c];
                v.w = cb*((const float*)&t4[3])[c] + cc*o[3][c];
                *(float4*)(S2 + (tj0+c)*PPITCH + ti0) = v;
            }
        }
    }
    __syncthreads();
    // mm3: Y = ca*X + S2 @ X  -> S1 (full grid);  Y^T -> XT
    mmP<KAHAN>(S2, X, o, i0, j0);
    #pragma unroll
    for (int r = 0; r < 4; r++) {
        float4 x = *(const float4*)(X + (i0+r)*PPITCH + j0);
        o[r][0] += ca*x.x; o[r][1] += ca*x.y; o[r][2] += ca*x.z; o[r][3] += ca*x.w;
        *(float4*)(S1 + (i0+r)*PPITCH + j0) = make_float4(o[r][0], o[r][1], o[r][2], o[r][3]);
    }
    if (needT) {
        #pragma unroll
        for (int c = 0; c < 4; c++)
            *(float4*)(XT + (j0+c)*PPITCH + i0) = make_float4(o[0][c], o[1][c], o[2][c], o[3][c]);
    }
    __syncthreads();
}

__global__ __launch_bounds__(256) void pe_kernel()
{
    extern __shared__ float sm[];
    float* X  = sm;
    float* XT = sm +   64*PPITCH;
    float* S1 = sm + 2*64*PPITCH;
    float* S2 = sm + 3*64*PPITCH;
    __shared__ float red[8];
    __shared__ float snorm;

    int tid = threadIdx.x;
    int tx = tid & 15, ty = tid >> 4;
    int i0 = ty*4, j0 = tx*4;
    float* gp = g_chunkS + (size_t)blockIdx.x * 4096;

    // triangle tile assignment: threads 0..135 -> (ta,tb), 0 <= ta <= tb <= 15
    bool act = (tid < 136);
    int ta = 0, tb = 0;
    if (act) {
        int rem = tid;
        while (rem >= 16 - ta) { rem -= 16 - ta; ta++; }
        tb = ta + rem;
    }
    int ti0 = ta*4, tj0 = tb*4;

    // load (vectorized) + Frobenius norm
    float lsum = 0.f;
    for (int i = tid; i < 1024; i += 256) {
        float4 f = ((const float4*)gp)[i];
        int row = i >> 4, c4 = (i & 15) * 4;
        *(float4*)(X + row*PPITCH + c4) = f;
        lsum += f.x*f.x + f.y*f.y + f.z*f.z + f.w*f.w;
    }
    #pragma unroll
    for (int m = 16; m >= 1; m >>= 1) lsum += __shfl_xor_sync(0xffffffffu, lsum, m);
    if ((tid & 31) == 0) red[tid >> 5] = lsum;
    __syncthreads();
    if (tid < 8) {
        float r2 = red[tid];
        r2 += __shfl_xor_sync(0xffu, r2, 4);
        r2 += __shfl_xor_sync(0xffu, r2, 2);
        r2 += __shfl_xor_sync(0xffu, r2, 1);
        if (tid == 0) snorm = 1.f/((sqrtf(r2) + 1e-7f)*1.01f);
    }
    __syncthreads();
    // scale in place + build X^T
    {
        float sc = snorm;
        float t[4][4];
        #pragma unroll
        for (int r = 0; r < 4; r++) {
            float4 f = *(const float4*)(X + (i0+r)*PPITCH + j0);
            t[r][0] = f.x*sc; t[r][1] = f.y*sc; t[r][2] = f.z*sc; t[r][3] = f.w*sc;
            *(float4*)(X + (i0+r)*PPITCH + j0) = make_float4(t[r][0], t[r][1], t[r][2], t[r][3]);
        }
        #pragma unroll
        for (int c = 0; c < 4; c++)
            *(float4*)(XT + (j0+c)*PPITCH + i0) = make_float4(t[0][c], t[1][c], t[2][c], t[3][c]);
    }
    __syncthreads();

    // iters 0-1: paired-product Kahan (amplified ~124x / ~30x downstream)
    pe_iterT<true>(X, XT, S1, S2, i0, j0, ti0, tj0, act, PEC[0][0], PEC[0][1], PEC[0][2], true);
    { float* tmp = X; X = S1; S1 = tmp; }
    pe_iterT<true>(X, XT, S1, S2, i0, j0, ti0, tj0, act, PEC[1][0], PEC[1][1], PEC[1][2], true);
    { float* tmp = X; X = S1; S1 = tmp; }
    // iters 2-4: plain split accumulators
    #pragma unroll 1
    for (int it = 2; it < 5; it++) {
        pe_iterT<false>(X, XT, S1, S2, i0, j0, ti0, tj0, act,
                        PEC[it][0], PEC[it][1], PEC[it][2], it < 4);
        float* tmp = X; X = S1; S1 = tmp;
    }

    #pragma unroll
    for (int r = 0; r < 4; r++) {
        float4 f = *(const float4*)(X + (i0+r)*PPITCH + j0);
        *(float4*)(gp + (i0+r)*64 + j0) = f;
    }
}

// ---------------- per-chunk: memory scan M_t = a_t M_{t-1} + orth_t ; y_t = M_t q_t ----------------
// v-partitioned: grid (Bsz*Hn, 4); all global I/O float4.
__global__ __launch_bounds__(256) void memscan_kernel(const float* __restrict__ qbuf, int n)
{
    __shared__ float qs[64*64];
    __shared__ float al[64];
    int bx = blockIdx.x;
    int b = bx >> 4, h = bx & 15;
    int v0 = blockIdx.y * 16;
    int tid = threadIdx.x;
    int v_loc = tid >> 4, kq = tid & 15;

    for (int i = tid; i < 1024; i += 256) {
        int t = i >> 4, c4 = (i & 15)*4;
        *(float4*)(qs + t*64 + c4) =
            *(const float4*)(qbuf + (size_t)(b*Tlen + n*CSz + t)*Cdim + h*Dd + c4);
    }
    if (tid < 64) al[tid] = g_alpha[(b*Tlen + n*CSz + tid)*Hn + h];
    float4 mreg = *(const float4*)(g_M + (size_t)(b*Hn + h)*4096 + (v0+v_loc)*64 + kq*4);
    __syncthreads();

    for (int t = 0; t < 64; t++) {
        float a = al[t];
        float4 cs = *(const float4*)(g_chunkS + ((((size_t)b*CSz + t)*Hn + h)*Dd + (v0+v_loc))*Dd + kq*4);
        mreg.x = a*mreg.x + cs.x;
        mreg.y = a*mreg.y + cs.y;
        mreg.z = a*mreg.z + cs.z;
        mreg.w = a*mreg.w + cs.w;
        float4 q4 = *(const float4*)(qs + t*64 + kq*4);
        float p = mreg.x*q4.x + mreg.y*q4.y + mreg.z*q4.z + mreg.w*q4.w;
        p += __shfl_xor_sync(0xffffffffu, p, 1);
        p += __shfl_xor_sync(0xffffffffu, p, 2);
        p += __shfl_xor_sync(0xffffffffu, p, 4);
        p += __shfl_xor_sync(0xffffffffu, p, 8);
        if (kq == 0)
            g_y[(size_t)(b*Tlen + n*CSz + t)*Cdim + h*Dd + v0 + v_loc] = p;
    }
    *(float4*)(g_M + (size_t)(b*Hn + h)*4096 + (v0+v_loc)*64 + kq*4) = mreg;
}

// ---------------- launch ----------------
extern "C" void kernel_launch(void* const* d_in, const int* in_sizes, int n_in,
                              void* d_out, int out_size)
{
    const float* x   = (const float*)d_in[0];
    const float* Wq  = (const float*)d_in[1];
    const float* Wk  = (const float*)d_in[2];
    const float* Wv  = (const float*)d_in[3];
    const float* Wo  = (const float*)d_in[4];
    const float* cqw = (const float*)d_in[5];
    const float* cqb = (const float*)d_in[6];
    const float* ckw = (const float*)d_in[7];
    const float* ckb = (const float*)d_in[8];
    const float* cvw = (const float*)d_in[9];
    const float* cvb = (const float*)d_in[10];
    const float* Wa  = (const float*)d_in[11];
    const float* We  = (const float*)d_in[12];
    const float* Wt  = (const float*)d_in[13];
    const float* Wg  = (const float*)d_in[14];
    float* out = (float*)d_out;

    cudaFuncSetAttribute(pe_kernel, cudaFuncAttributeMaxDynamicSharedMemorySize, PE_SMEM);

    float *pxq, *pxk, *pxv, *pq, *pk, *pv, *py, *pyn;
    cudaGetSymbolAddress((void**)&pxq, g_xq);
    cudaGetSymbolAddress((void**)&pxk, g_xk);
    cudaGetSymbolAddress((void**)&pxv, g_xv);
    cudaGetSymbolAddress((void**)&pq,  g_q);
    cudaGetSymbolAddress((void**)&pk,  g_k);
    cudaGetSymbolAddress((void**)&pv,  g_v);
    cudaGetSymbolAddress((void**)&py,  g_y);
    cudaGetSymbolAddress((void**)&pyn, g_yn);

    zero_state_kernel<<<(Bsz*Hn*Dd*Dd + 255)/256, 256>>>();

    dim3 gq(Cdim/64, (Bsz*Tlen)/64, 3);
    sgemm_nt_qkv<<<gq, 256>>>(x, Wq, Wk, Wv, pxq, pxk, pxv, Bsz*Tlen, Cdim, Cdim);
    gates_kernel<<<Bsz*Tlen, 256>>>(x, Wa, We, Wt, Wg);
    conv_feat_kernel<<<Bsz*Tlen, 256>>>(pxq, cqw, cqb, pq, 1);
    conv_feat_kernel<<<Bsz*Tlen, 256>>>(pxk, ckw, ckb, pk, 1);
    conv_feat_kernel<<<Bsz*Tlen, 256>>>(pxv, cvw, cvb, pv, 0);

    dim3 gscan(Bsz*Hn, 4);
    for (int n = 0; n < NCH; n++) {
        chunk_err_kernel<<<gscan, 256>>>(pk, pv, n);
        pe_kernel<<<Bsz*CSz*Hn, 256, PE_SMEM>>>();
        memscan_kernel<<<gscan, 256>>>(pq, n);
    }

    ynorm_kernel<<<Bsz*Tlen, 256>>>(py, pyn);
    dim3 gg(Cdim/64, (Bsz*Tlen)/64);
    sgemm_nt<<<gg, 256>>>(pyn, Wo, out, Bsz*Tlen, Cdim, Cdim);
}